// round 5
// baseline (speedup 1.0000x reference)
#include <cuda_runtime.h>
#include <cuda_bf16.h>

#define B_     16
#define S_     4096
#define D_     512
#define PE_DIM 256

// Fused: each block (1024 consecutive float4 = 8 rows of one batch) computes
// its batch's length from the mask (L2-resident, 16KB/row), then does the
// elementwise PE add. Single launch — no producer kernel, no PDL.
__global__ void __launch_bounds__(256) fused_pe_kernel(const float4* __restrict__ x,
                                                       const float* __restrict__ pe,
                                                       const int* __restrict__ mask,
                                                       float4* __restrict__ out) {
    const size_t base = (size_t)blockIdx.x * 1024 + threadIdx.x;
    const int b = blockIdx.x >> 9;               // 512 blocks per batch

    // ---- front-batch the DRAM stream (x) ----
    float4 xv[4];
    #pragma unroll
    for (int i = 0; i < 4; i++)
        xv[i] = __ldcs(&x[base + (size_t)i * 256]);

    // ---- length of batch b: count zeros in mask[b, :] (4096 ints, L2-hit) ----
    const int4* mrow = reinterpret_cast<const int4*>(mask + (size_t)b * S_);
    int cnt = 0;
    #pragma unroll
    for (int k = 0; k < 4; k++) {
        int4 v = __ldg(&mrow[threadIdx.x + k * 256]);
        cnt += (v.x == 0) + (v.y == 0) + (v.z == 0) + (v.w == 0);
    }
    #pragma unroll
    for (int off = 16; off > 0; off >>= 1)
        cnt += __shfl_down_sync(0xFFFFFFFFu, cnt, off);

    __shared__ int ssum[8];
    __shared__ int slen;
    const int lane = threadIdx.x & 31;
    const int wid  = threadIdx.x >> 5;
    if (lane == 0) ssum[wid] = cnt;
    __syncthreads();
    if (wid == 0) {
        int v = (lane < 8) ? ssum[lane] : 0;
        #pragma unroll
        for (int off = 4; off > 0; off >>= 1)
            v += __shfl_down_sync(0xFFFFFFFFu, v, off);
        if (lane == 0) slen = v;
    }
    __syncthreads();
    const int len = slen;

    // ---- elementwise add: base PE + reversed PE (pe table is L2-resident) ----
    #pragma unroll
    for (int i = 0; i < 4; i++) {
        const size_t t = base + (size_t)i * 256;
        const int q  = (int)(t & 127);           // float4 index within D row
        const int s  = (int)((t >> 7) & (S_ - 1));
        const int d2 = (q * 4) & (PE_DIM - 1);

        float4 bv = *reinterpret_cast<const float4*>(pe + (size_t)s * PE_DIM + d2);
        float4 o;
        o.x = xv[i].x + bv.x;
        o.y = xv[i].y + bv.y;
        o.z = xv[i].z + bv.z;
        o.w = xv[i].w + bv.w;

        if (s < len) {
            const int idx = len - 1 - s;
            float4 rv = *reinterpret_cast<const float4*>(
                pe + (size_t)idx * PE_DIM + (252 - d2));
            o.x += rv.w;
            o.y += rv.z;
            o.z += rv.y;
            o.w += rv.x;
        }
        __stcs(&out[t], o);
    }
}

extern "C" void kernel_launch(void* const* d_in, const int* in_sizes, int n_in,
                              void* d_out, int out_size) {
    const float* x    = (const float*)d_in[0];
    const int*   mask = (const int*)d_in[1];
    const float* pe   = (const float*)d_in[2];
    float* out = (float*)d_out;

    const size_t total4 = (size_t)B_ * S_ * (D_ / 4);   // 8,388,608 float4
    const unsigned blocks = (unsigned)(total4 / 1024);  // 8192

    fused_pe_kernel<<<blocks, 256>>>((const float4*)x, pe, mask, (float4*)out);
}

// round 6
// speedup vs baseline: 1.1454x; 1.1454x over previous
#include <cuda_runtime.h>
#include <cuda_bf16.h>

#define B_     16
#define S_     4096
#define D_     512
#define PE_DIM 256

__device__ int g_lengths[B_];

// One block per batch row, 1024 threads, one int4 per thread.
// Fires the PDL trigger FIRST so the consumer grid launches and runs its
// pre-sync phase concurrently with this kernel.
__global__ void __launch_bounds__(1024) lengths_kernel(const int* __restrict__ mask) {
    cudaTriggerProgrammaticLaunchCompletion();

    const int b = blockIdx.x;
    const int4 v = reinterpret_cast<const int4*>(mask + (size_t)b * S_)[threadIdx.x];
    int cnt = (v.x == 0) + (v.y == 0) + (v.z == 0) + (v.w == 0);

    #pragma unroll
    for (int off = 16; off > 0; off >>= 1)
        cnt += __shfl_down_sync(0xFFFFFFFFu, cnt, off);

    __shared__ int smem[32];
    const int lane = threadIdx.x & 31;
    const int wid  = threadIdx.x >> 5;
    if (lane == 0) smem[wid] = cnt;
    __syncthreads();
    if (wid == 0) {
        int t = smem[lane];                     // 32 warps exactly
        #pragma unroll
        for (int off = 16; off > 0; off >>= 1)
            t += __shfl_down_sync(0xFFFFFFFFu, t, off);
        if (lane == 0) g_lengths[b] = t;
    }
}

// 4 float4 per thread, front-batched loads, then PDL-sync, then finish.
__global__ void __launch_bounds__(256) pe_add_kernel(const float4* __restrict__ x,
                                                     const float* __restrict__ pe,
                                                     float4* __restrict__ out) {
    const size_t base = (size_t)blockIdx.x * 1024 + threadIdx.x;

    // ---- phase 1: independent of g_lengths (overlaps the producer) ----
    float4 xv[4], bv[4];
    int s[4], d2[4];
    #pragma unroll
    for (int i = 0; i < 4; i++) {
        size_t t = base + (size_t)i * 256;
        xv[i] = __ldcs(&x[t]);                   // streaming: don't pollute L2
        int q = (int)(t & 127);                  // float4 index within D row
        size_t row = t >> 7;                     // b*S + s
        s[i]  = (int)(row & (S_ - 1));
        d2[i] = (q * 4) & (PE_DIM - 1);
        bv[i] = *reinterpret_cast<const float4*>(pe + (size_t)s[i] * PE_DIM + d2[i]);
    }
    const int b = (int)(base >> 19);             // 4096*128 float4 per batch

    // ---- wait for lengths_kernel, then finish ----
    cudaGridDependencySynchronize();
    const int len = g_lengths[b];

    #pragma unroll
    for (int i = 0; i < 4; i++) {
        float4 o;
        o.x = xv[i].x + bv[i].x;
        o.y = xv[i].y + bv[i].y;
        o.z = xv[i].z + bv[i].z;
        o.w = xv[i].w + bv[i].w;
        if (s[i] < len) {
            int idx = len - 1 - s[i];
            float4 rv = *reinterpret_cast<const float4*>(
                pe + (size_t)idx * PE_DIM + (252 - d2[i]));
            o.x += rv.w;
            o.y += rv.z;
            o.z += rv.y;
            o.w += rv.x;
        }
        __stcs(&out[base + (size_t)i * 256], o);
    }
}

extern "C" void kernel_launch(void* const* d_in, const int* in_sizes, int n_in,
                              void* d_out, int out_size) {
    const float* x    = (const float*)d_in[0];
    const int*   mask = (const int*)d_in[1];
    const float* pe   = (const float*)d_in[2];
    float* out = (float*)d_out;

    lengths_kernel<<<B_, 1024>>>(mask);

    const size_t total4 = (size_t)B_ * S_ * (D_ / 4);   // 8,388,608 float4
    const unsigned blocks = (unsigned)(total4 / 1024);  // 8192

    cudaLaunchConfig_t cfg = {};
    cfg.gridDim  = dim3(blocks, 1, 1);
    cfg.blockDim = dim3(256, 1, 1);
    cfg.dynamicSmemBytes = 0;
    cfg.stream = 0;
    cudaLaunchAttribute attrs[1];
    attrs[0].id = cudaLaunchAttributeProgrammaticStreamSerialization;
    attrs[0].val.programmaticStreamSerializationAllowed = 1;
    cfg.attrs = attrs;
    cfg.numAttrs = 1;

    cudaLaunchKernelEx(&cfg, pe_add_kernel,
                       (const float4*)x, pe, (float4*)out);
}